// round 5
// baseline (speedup 1.0000x reference)
#include <cuda_runtime.h>
#include <math_constants.h>

// Output spatial: 28x28, batch 8, out channels 256.
#define HW   28
#define NB   8
#define PLANE (HW*HW)        // 784
#define PLANE4 (PLANE/4)     // 196

// Pooled scratch (channel-tiling means we pool once, reuse across replicas).
__device__ float g_p1[NB*128*PLANE]; // pool2 of (8,128,56,56)
__device__ float g_p2[NB*64 *PLANE]; // pool4 of (8,64,112,112)
__device__ float g_p3[NB*32 *PLANE]; // pool8 of (8,32,224,224)
__device__ float g_p4[NB*16 *PLANE]; // pool16 of (8,16,448,448)

// K = pool window/stride, C = channels, TAG selects destination scratch.
template<int K, int C, int TAG>
__global__ void pool_kernel(const float* __restrict__ in) {
    constexpr int TOTAL = NB * C * PLANE;
    int idx = blockIdx.x * blockDim.x + threadIdx.x;
    if (idx >= TOTAL) return;

    int w  = idx % HW;
    int h  = (idx / HW) % HW;
    long bc = idx / PLANE;            // b*C + c
    constexpr int WIN = HW * K;       // input width/height
    const float* p = in + (bc * WIN + (long)h * K) * WIN + (long)w * K;

    float m = -CUDART_INF_F;
    for (int r = 0; r < K; r++) {
        const float* row = p + (long)r * WIN;
        if constexpr (K == 2) {
            float2 v = *reinterpret_cast<const float2*>(row);
            m = fmaxf(m, fmaxf(v.x, v.y));
        } else {
            #pragma unroll
            for (int j = 0; j < K / 4; j++) {
                float4 v = reinterpret_cast<const float4*>(row)[j];
                m = fmaxf(m, fmaxf(fmaxf(v.x, v.y), fmaxf(v.z, v.w)));
            }
        }
    }

    float* out;
    if constexpr (TAG == 1) out = g_p1;
    else if constexpr (TAG == 2) out = g_p2;
    else if constexpr (TAG == 3) out = g_p3;
    else out = g_p4;
    out[idx] = m;
}

__global__ void combine_kernel(const float* __restrict__ ff, float* __restrict__ out) {
    constexpr int TOTAL4 = NB * 256 * PLANE4;   // 401408
    int idx4 = blockIdx.x * blockDim.x + threadIdx.x;
    if (idx4 >= TOTAL4) return;

    int s = idx4 % PLANE4;
    int c = (idx4 / PLANE4) % 256;
    int b = idx4 / (PLANE4 * 256);

    const float4* P1 = reinterpret_cast<const float4*>(g_p1);
    const float4* P2 = reinterpret_cast<const float4*>(g_p2);
    const float4* P3 = reinterpret_cast<const float4*>(g_p3);
    const float4* P4 = reinterpret_cast<const float4*>(g_p4);

    float4 a = P1[(b * 128 + (c & 127)) * PLANE4 + s];
    float4 d = P2[(b * 64  + (c & 63))  * PLANE4 + s];
    float4 e = P3[(b * 32  + (c & 31))  * PLANE4 + s];
    float4 g = P4[(b * 16  + (c & 15))  * PLANE4 + s];
    float4 f = reinterpret_cast<const float4*>(ff)[idx4];

    float4 o;
    o.x = fmaxf(a.x + d.x + e.x + g.x + f.x, 0.0f);
    o.y = fmaxf(a.y + d.y + e.y + g.y + f.y, 0.0f);
    o.z = fmaxf(a.z + d.z + e.z + g.z + f.z, 0.0f);
    o.w = fmaxf(a.w + d.w + e.w + g.w + f.w, 0.0f);
    reinterpret_cast<float4*>(out)[idx4] = o;
}

extern "C" void kernel_launch(void* const* d_in, const int* in_sizes, int n_in,
                              void* d_out, int out_size) {
    // Map inputs by unique element count (robust to ordering).
    const float *t1 = nullptr, *t2 = nullptr, *t3 = nullptr, *t4 = nullptr, *ff = nullptr;
    for (int i = 0; i < n_in; i++) {
        switch (in_sizes[i]) {
            case 8*128*56*56:   t1 = (const float*)d_in[i]; break;   // 3211264
            case 8*64*112*112:  t2 = (const float*)d_in[i]; break;   // 6422528
            case 8*32*224*224:  t3 = (const float*)d_in[i]; break;   // 12845056
            case 8*16*448*448:  t4 = (const float*)d_in[i]; break;   // 25690112
            case 8*256*28*28:   ff = (const float*)d_in[i]; break;   // 1605632
        }
    }

    const int T = 256;
    pool_kernel<2, 128, 1><<<(NB*128*PLANE + T - 1) / T, T>>>(t1);
    pool_kernel<4, 64,  2><<<(NB*64 *PLANE + T - 1) / T, T>>>(t2);
    pool_kernel<8, 32,  3><<<(NB*32 *PLANE + T - 1) / T, T>>>(t3);
    pool_kernel<16, 16, 4><<<(NB*16 *PLANE + T - 1) / T, T>>>(t4);

    combine_kernel<<<(NB*256*PLANE4 + T - 1) / T, T>>>(ff, (float*)d_out);
}

// round 6
// speedup vs baseline: 1.0447x; 1.0447x over previous
#include <cuda_runtime.h>
#include <math_constants.h>

// Output spatial: 28x28, batch 8, out channels 256.
#define HW   28
#define NB   8
#define PLANE (HW*HW)        // 784
#define PLANE4 (PLANE/4)     // 196

// Pooled scratch (channel-tiling means we pool once, reuse across replicas).
__device__ float g_p1[NB*128*PLANE]; // pool2  of (8,128,56,56)
__device__ float g_p2[NB*64 *PLANE]; // pool4  of (8,64,112,112)
__device__ float g_p3[NB*32 *PLANE]; // pool8  of (8,32,224,224)
__device__ float g_p4[NB*16 *PLANE]; // pool16 of (8,16,448,448)

// Block-range dispatch for the fused pooling kernel.
// Seg A: k=16, t4, warp/output    : 100352 outputs * 32 thr / 256 = 12544 blocks
// Seg B: k=8,  t3, 8 lanes/output : 200704 * 8 / 256             =  6272 blocks
// Seg C: k=4,  t2, 4 lanes/output : 401408 * 4 / 256             =  6272 blocks
// Seg D: k=2,  t1, thread/output  : 802816 / 256                 =  3136 blocks
#define A_BLOCKS 12544
#define B_BLOCKS 6272
#define C_BLOCKS 6272
#define D_BLOCKS 3136
#define POOL_BLOCKS (A_BLOCKS + B_BLOCKS + C_BLOCKS + D_BLOCKS)

__device__ __forceinline__ float max4(float4 v) {
    return fmaxf(fmaxf(v.x, v.y), fmaxf(v.z, v.w));
}

__global__ void __launch_bounds__(256) fused_pool_kernel(
    const float* __restrict__ t1, const float* __restrict__ t2,
    const float* __restrict__ t3, const float* __restrict__ t4)
{
    int bid = blockIdx.x;
    int tid = threadIdx.x;

    if (bid < A_BLOCKS) {
        // ---- k=16 pool of (8,16,448,448): one warp per output element ----
        int oidx = (bid * 256 + tid) >> 5;        // 0..100351
        int lane = tid & 31;
        int w = oidx % HW;
        int h = (oidx / HW) % HW;
        long bc = oidx / PLANE;                   // b*16 + c
        int r = lane >> 1;                        // row 0..15
        int q = lane & 1;                         // half-row 0..1
        const float* p = t4 + (bc * 448 + (long)(h * 16 + r)) * 448
                            + (long)w * 16 + q * 8;
        float4 v0 = *reinterpret_cast<const float4*>(p);
        float4 v1 = *reinterpret_cast<const float4*>(p + 4);
        float m = fmaxf(max4(v0), max4(v1));
        #pragma unroll
        for (int k = 16; k >= 1; k >>= 1)
            m = fmaxf(m, __shfl_xor_sync(0xffffffffu, m, k));
        if (lane == 0) g_p4[oidx] = m;
        return;
    }
    bid -= A_BLOCKS;

    if (bid < B_BLOCKS) {
        // ---- k=8 pool of (8,32,224,224): 8 lanes per output ----
        int t = bid * 256 + tid;
        int oidx = t >> 3;                        // 0..200703
        int g = tid & 7;                          // row within window
        int w = oidx % HW;
        int h = (oidx / HW) % HW;
        long bc = oidx / PLANE;                   // b*32 + c
        const float* p = t3 + (bc * 224 + (long)(h * 8 + g)) * 224 + (long)w * 8;
        float4 v0 = *reinterpret_cast<const float4*>(p);
        float4 v1 = *reinterpret_cast<const float4*>(p + 4);
        float m = fmaxf(max4(v0), max4(v1));
        #pragma unroll
        for (int k = 4; k >= 1; k >>= 1)
            m = fmaxf(m, __shfl_xor_sync(0xffffffffu, m, k));
        if (g == 0) g_p3[oidx] = m;
        return;
    }
    bid -= B_BLOCKS;

    if (bid < C_BLOCKS) {
        // ---- k=4 pool of (8,64,112,112): 4 lanes per output ----
        int t = bid * 256 + tid;
        int oidx = t >> 2;                        // 0..401407
        int g = tid & 3;                          // row within window
        int w = oidx % HW;
        int h = (oidx / HW) % HW;
        long bc = oidx / PLANE;                   // b*64 + c
        const float* p = t2 + (bc * 112 + (long)(h * 4 + g)) * 112 + (long)w * 4;
        float4 v = *reinterpret_cast<const float4*>(p);
        float m = max4(v);
        #pragma unroll
        for (int k = 2; k >= 1; k >>= 1)
            m = fmaxf(m, __shfl_xor_sync(0xffffffffu, m, k));
        if (g == 0) g_p2[oidx] = m;
        return;
    }
    bid -= C_BLOCKS;

    {
        // ---- k=2 pool of (8,128,56,56): one thread per output ----
        int oidx = bid * 256 + tid;               // 0..802815
        int w = oidx % HW;
        int h = (oidx / HW) % HW;
        long bc = oidx / PLANE;                   // b*128 + c
        const float* p = t1 + (bc * 56 + (long)(h * 2)) * 56 + (long)w * 2;
        float2 a = *reinterpret_cast<const float2*>(p);
        float2 b = *reinterpret_cast<const float2*>(p + 56);
        g_p1[oidx] = fmaxf(fmaxf(a.x, a.y), fmaxf(b.x, b.y));
    }
}

__global__ void __launch_bounds__(256) combine_kernel(
    const float* __restrict__ ff, float* __restrict__ out)
{
    constexpr int TOTAL4 = NB * 256 * PLANE4;   // 401408
    int idx4 = blockIdx.x * blockDim.x + threadIdx.x;
    if (idx4 >= TOTAL4) return;

    int s = idx4 % PLANE4;
    int c = (idx4 / PLANE4) % 256;
    int b = idx4 / (PLANE4 * 256);

    const float4* P1 = reinterpret_cast<const float4*>(g_p1);
    const float4* P2 = reinterpret_cast<const float4*>(g_p2);
    const float4* P3 = reinterpret_cast<const float4*>(g_p3);
    const float4* P4 = reinterpret_cast<const float4*>(g_p4);

    float4 a = P1[(b * 128 + (c & 127)) * PLANE4 + s];
    float4 d = P2[(b * 64  + (c & 63))  * PLANE4 + s];
    float4 e = P3[(b * 32  + (c & 31))  * PLANE4 + s];
    float4 g = P4[(b * 16  + (c & 15))  * PLANE4 + s];
    float4 f = reinterpret_cast<const float4*>(ff)[idx4];

    float4 o;
    o.x = fmaxf(a.x + d.x + e.x + g.x + f.x, 0.0f);
    o.y = fmaxf(a.y + d.y + e.y + g.y + f.y, 0.0f);
    o.z = fmaxf(a.z + d.z + e.z + g.z + f.z, 0.0f);
    o.w = fmaxf(a.w + d.w + e.w + g.w + f.w, 0.0f);
    reinterpret_cast<float4*>(out)[idx4] = o;
}

extern "C" void kernel_launch(void* const* d_in, const int* in_sizes, int n_in,
                              void* d_out, int out_size) {
    // Map inputs by unique element count (robust to ordering).
    const float *t1 = nullptr, *t2 = nullptr, *t3 = nullptr, *t4 = nullptr, *ff = nullptr;
    for (int i = 0; i < n_in; i++) {
        switch (in_sizes[i]) {
            case 8*128*56*56:   t1 = (const float*)d_in[i]; break;   // 3211264
            case 8*64*112*112:  t2 = (const float*)d_in[i]; break;   // 6422528
            case 8*32*224*224:  t3 = (const float*)d_in[i]; break;   // 12845056
            case 8*16*448*448:  t4 = (const float*)d_in[i]; break;   // 25690112
            case 8*256*28*28:   ff = (const float*)d_in[i]; break;   // 1605632
        }
    }

    fused_pool_kernel<<<POOL_BLOCKS, 256>>>(t1, t2, t3, t4);

    const int T = 256;
    combine_kernel<<<(NB*256*PLANE4 + T - 1) / T, T>>>(ff, (float*)d_out);
}

// round 7
// speedup vs baseline: 1.1001x; 1.0530x over previous
#include <cuda_runtime.h>
#include <math_constants.h>

// Output spatial: 28x28, batch 8, out channels 256.
#define HW   28
#define NB   8
#define PLANE (HW*HW)        // 784
#define PLANE4 (PLANE/4)     // 196

// Pooled scratch (channel-tiling means we pool once, reuse across replicas).
__device__ float g_p1[NB*128*PLANE]; // pool2  of (8,128,56,56)
__device__ float g_p2[NB*64 *PLANE]; // pool4  of (8,64,112,112)
__device__ float g_p3[NB*32 *PLANE]; // pool8  of (8,32,224,224)
__device__ float g_p4[NB*16 *PLANE]; // pool16 of (8,16,448,448)

// Block-range dispatch (256 threads/block):
// Seg A: k=16, t4, 16 lanes/output (1 row each, 4xLDG128): 100352*16/256 = 6272
// Seg B: k=8,  t3, 4 lanes/output (2 rows each, 4xLDG128): 200704*4/256  = 3136
// Seg C: k=4,  t2, 1 thread/output (4 rows, 4xLDG128)    : 401408/256    = 1568
// Seg D: k=2,  t1, 1 thread / 2 outputs (2xLDG128)       : 401408/256    = 1568
#define A_BLOCKS 6272
#define B_BLOCKS 3136
#define C_BLOCKS 1568
#define D_BLOCKS 1568
#define POOL_BLOCKS (A_BLOCKS + B_BLOCKS + C_BLOCKS + D_BLOCKS)

__device__ __forceinline__ float max4(float4 v) {
    return fmaxf(fmaxf(v.x, v.y), fmaxf(v.z, v.w));
}

__global__ void __launch_bounds__(256) fused_pool_kernel(
    const float* __restrict__ t1, const float* __restrict__ t2,
    const float* __restrict__ t3, const float* __restrict__ t4)
{
    int bid = blockIdx.x;
    int tid = threadIdx.x;

    if (bid < A_BLOCKS) {
        // ---- k=16 pool of (8,16,448,448): 16 lanes per output, 1 row/lane ----
        int t = bid * 256 + tid;
        int oidx = t >> 4;                        // 0..100351
        int r = t & 15;                           // row within 16x16 window
        int w = oidx % HW;
        int h = (oidx / HW) % HW;
        long bc = oidx / PLANE;                   // b*16 + c
        const float* p = t4 + (bc * 448 + (long)(h * 16 + r)) * 448 + (long)w * 16;
        float4 v0 = __ldcs(reinterpret_cast<const float4*>(p));
        float4 v1 = __ldcs(reinterpret_cast<const float4*>(p + 4));
        float4 v2 = __ldcs(reinterpret_cast<const float4*>(p + 8));
        float4 v3 = __ldcs(reinterpret_cast<const float4*>(p + 12));
        float m = fmaxf(fmaxf(max4(v0), max4(v1)), fmaxf(max4(v2), max4(v3)));
        #pragma unroll
        for (int k = 8; k >= 1; k >>= 1)          // reduce within 16-lane group
            m = fmaxf(m, __shfl_xor_sync(0xffffffffu, m, k));
        if (r == 0) g_p4[oidx] = m;
        return;
    }
    bid -= A_BLOCKS;

    if (bid < B_BLOCKS) {
        // ---- k=8 pool of (8,32,224,224): 4 lanes per output, 2 rows/lane ----
        int t = bid * 256 + tid;
        int oidx = t >> 2;                        // 0..200703
        int g = t & 3;                            // row-pair within window
        int w = oidx % HW;
        int h = (oidx / HW) % HW;
        long bc = oidx / PLANE;                   // b*32 + c
        const float* p = t3 + (bc * 224 + (long)(h * 8 + 2 * g)) * 224 + (long)w * 8;
        float4 v0 = __ldcs(reinterpret_cast<const float4*>(p));
        float4 v1 = __ldcs(reinterpret_cast<const float4*>(p + 4));
        float4 v2 = __ldcs(reinterpret_cast<const float4*>(p + 224));
        float4 v3 = __ldcs(reinterpret_cast<const float4*>(p + 228));
        float m = fmaxf(fmaxf(max4(v0), max4(v1)), fmaxf(max4(v2), max4(v3)));
        #pragma unroll
        for (int k = 2; k >= 1; k >>= 1)          // reduce within 4-lane group
            m = fmaxf(m, __shfl_xor_sync(0xffffffffu, m, k));
        if (g == 0) g_p3[oidx] = m;
        return;
    }
    bid -= B_BLOCKS;

    if (bid < C_BLOCKS) {
        // ---- k=4 pool of (8,64,112,112): 1 thread per output, 4 rows ----
        int oidx = bid * 256 + tid;               // 0..401407
        int w = oidx % HW;
        int h = (oidx / HW) % HW;
        long bc = oidx / PLANE;                   // b*64 + c
        const float* p = t2 + (bc * 112 + (long)(h * 4)) * 112 + (long)w * 4;
        float4 v0 = __ldcs(reinterpret_cast<const float4*>(p));
        float4 v1 = __ldcs(reinterpret_cast<const float4*>(p + 112));
        float4 v2 = __ldcs(reinterpret_cast<const float4*>(p + 224));
        float4 v3 = __ldcs(reinterpret_cast<const float4*>(p + 336));
        g_p2[oidx] = fmaxf(fmaxf(max4(v0), max4(v1)), fmaxf(max4(v2), max4(v3)));
        return;
    }
    bid -= C_BLOCKS;

    {
        // ---- k=2 pool of (8,128,56,56): 1 thread per 2 horizontal outputs ----
        int pi = bid * 256 + tid;                 // 0..401407 (output pairs)
        constexpr int HALFROW = HW / 2;           // 14 pairs per output row
        constexpr int PPLANE = PLANE / 2;         // 392 pairs per plane
        int s  = pi % PPLANE;
        int w2 = s % HALFROW;
        int h  = s / HALFROW;
        long bc = pi / PPLANE;                    // b*128 + c
        const float* p = t1 + (bc * 56 + (long)(h * 2)) * 56 + (long)w2 * 4;
        float4 a = __ldcs(reinterpret_cast<const float4*>(p));
        float4 b = __ldcs(reinterpret_cast<const float4*>(p + 56));
        float2 o;
        o.x = fmaxf(fmaxf(a.x, a.y), fmaxf(b.x, b.y));
        o.y = fmaxf(fmaxf(a.z, a.w), fmaxf(b.z, b.w));
        *reinterpret_cast<float2*>(g_p1 + bc * PLANE + h * HW + w2 * 2) = o;
    }
}

__global__ void __launch_bounds__(256) combine_kernel(
    const float* __restrict__ ff, float* __restrict__ out)
{
    constexpr int TOTAL4 = NB * 256 * PLANE4;   // 401408
    constexpr int HALF4  = TOTAL4 / 2;          // 200704 (= 4 batches worth)
    int idx4 = blockIdx.x * blockDim.x + threadIdx.x;
    if (idx4 >= HALF4) return;

    int s = idx4 % PLANE4;
    int c = (idx4 / PLANE4) % 256;
    int b = idx4 / (PLANE4 * 256);              // 0..3; second element is b+4

    const float4* P1 = reinterpret_cast<const float4*>(g_p1);
    const float4* P2 = reinterpret_cast<const float4*>(g_p2);
    const float4* P3 = reinterpret_cast<const float4*>(g_p3);
    const float4* P4 = reinterpret_cast<const float4*>(g_p4);
    const float4* FF = reinterpret_cast<const float4*>(ff);

    int i1 = (b * 128 + (c & 127)) * PLANE4 + s;
    int i2 = (b * 64  + (c & 63))  * PLANE4 + s;
    int i3 = (b * 32  + (c & 31))  * PLANE4 + s;
    int i4 = (b * 16  + (c & 15))  * PLANE4 + s;

    // Front-batch all 10 loads (2 output elements: batches b and b+4).
    float4 a0 = P1[i1],                     a1 = P1[i1 + 4*128*PLANE4];
    float4 d0 = P2[i2],                     d1 = P2[i2 + 4*64 *PLANE4];
    float4 e0 = P3[i3],                     e1 = P3[i3 + 4*32 *PLANE4];
    float4 g0 = P4[i4],                     g1 = P4[i4 + 4*16 *PLANE4];
    float4 f0 = __ldcs(FF + idx4),          f1 = __ldcs(FF + idx4 + HALF4);

    float4 o0, o1;
    o0.x = fmaxf(a0.x + d0.x + e0.x + g0.x + f0.x, 0.0f);
    o0.y = fmaxf(a0.y + d0.y + e0.y + g0.y + f0.y, 0.0f);
    o0.z = fmaxf(a0.z + d0.z + e0.z + g0.z + f0.z, 0.0f);
    o0.w = fmaxf(a0.w + d0.w + e0.w + g0.w + f0.w, 0.0f);
    o1.x = fmaxf(a1.x + d1.x + e1.x + g1.x + f1.x, 0.0f);
    o1.y = fmaxf(a1.y + d1.y + e1.y + g1.y + f1.y, 0.0f);
    o1.z = fmaxf(a1.z + d1.z + e1.z + g1.z + f1.z, 0.0f);
    o1.w = fmaxf(a1.w + d1.w + e1.w + g1.w + f1.w, 0.0f);
    reinterpret_cast<float4*>(out)[idx4] = o0;
    reinterpret_cast<float4*>(out)[idx4 + HALF4] = o1;
}

extern "C" void kernel_launch(void* const* d_in, const int* in_sizes, int n_in,
                              void* d_out, int out_size) {
    // Map inputs by unique element count (robust to ordering).
    const float *t1 = nullptr, *t2 = nullptr, *t3 = nullptr, *t4 = nullptr, *ff = nullptr;
    for (int i = 0; i < n_in; i++) {
        switch (in_sizes[i]) {
            case 8*128*56*56:   t1 = (const float*)d_in[i]; break;   // 3211264
            case 8*64*112*112:  t2 = (const float*)d_in[i]; break;   // 6422528
            case 8*32*224*224:  t3 = (const float*)d_in[i]; break;   // 12845056
            case 8*16*448*448:  t4 = (const float*)d_in[i]; break;   // 25690112
            case 8*256*28*28:   ff = (const float*)d_in[i]; break;   // 1605632
        }
    }

    fused_pool_kernel<<<POOL_BLOCKS, 256>>>(t1, t2, t3, t4);

    constexpr int HALF4 = (NB * 256 * PLANE4) / 2;   // 200704
    combine_kernel<<<(HALF4 + 255) / 256, 256>>>(ff, (float*)d_out);
}